// round 2
// baseline (speedup 1.0000x reference)
#include <cuda_runtime.h>
#include <cstdint>

// Problem constants (fixed by the reference).
#define N_KEYS   65536
#define EMB      1024
#define KSEL     512
#define BATCH    128
#define CAND_CAP 2048    // candidate capacity for the tie bin (expected ~540 used)

// -------- scratch (no allocations allowed: __device__ globals) --------
__device__ float        g_sims[N_KEYS];
__device__ unsigned int g_hist[65536];   // histogram over top-16 bits of ordered float
__device__ int          g_topk[KSEL];

// Monotone float -> uint transform: a > b  <=>  ford(a) > ford(b)
__device__ __forceinline__ unsigned int ford(float f) {
    unsigned int u = __float_as_uint(f);
    return (u & 0x80000000u) ? ~u : (u | 0x80000000u);
}

// ---------------------------------------------------------------------
// Kernel Z: zero the histogram (must precede sim kernel's atomics).
// ---------------------------------------------------------------------
__global__ void zero_hist_kernel() {
    int i = blockIdx.x * blockDim.x + threadIdx.x;
    g_hist[i] = 0u;
}

// ---------------------------------------------------------------------
// Kernel A: sims[n] = dot(keys[n], query) / ||keys[n]||  (+ histogram)
// One warp per key row. 8 warps / block, grid = 8192.
// ---------------------------------------------------------------------
__global__ void sim_kernel(const float* __restrict__ keys,
                           const float* __restrict__ query) {
    const int warp = threadIdx.x >> 5;
    const int lane = threadIdx.x & 31;
    const int n    = blockIdx.x * 8 + warp;

    const float4* k4 = reinterpret_cast<const float4*>(keys) + (size_t)n * (EMB / 4);
    const float4* q4 = reinterpret_cast<const float4*>(query);

    float dot = 0.f, sq = 0.f;
#pragma unroll
    for (int l = 0; l < 8; ++l) {
        float4 kv = k4[lane + 32 * l];
        float4 qv = __ldg(&q4[lane + 32 * l]);
        dot = fmaf(kv.x, qv.x, dot);
        dot = fmaf(kv.y, qv.y, dot);
        dot = fmaf(kv.z, qv.z, dot);
        dot = fmaf(kv.w, qv.w, dot);
        sq  = fmaf(kv.x, kv.x, sq);
        sq  = fmaf(kv.y, kv.y, sq);
        sq  = fmaf(kv.z, kv.z, sq);
        sq  = fmaf(kv.w, kv.w, sq);
    }
#pragma unroll
    for (int o = 16; o > 0; o >>= 1) {
        dot += __shfl_xor_sync(0xFFFFFFFFu, dot, o);
        sq  += __shfl_xor_sync(0xFFFFFFFFu, sq,  o);
    }
    if (lane == 0) {
        float nrm = __fsqrt_rn(fmaxf(sq, 1e-16f));   // max(norm, 1e-8)
        float sim = __fdiv_rn(dot, nrm);             // q-norm scale omitted (order-invariant)
        g_sims[n] = sim;
        atomicAdd(&g_hist[ford(sim) >> 16], 1u);
    }
}

// ---------------------------------------------------------------------
// Kernel B: single block, 1024 threads.
//   1) parallel suffix-scan of 65536-bin histogram -> rank-512 threshold
//   2) compact candidates (ord >= threshold) -> ~540 entries
//   3) bitonic sort 2048 packed keys (value desc, index asc) -> top 512
// ---------------------------------------------------------------------
__global__ void topk_kernel() {
    __shared__ int                s_sum[1024];     // chunk sums -> suffix sums
    __shared__ int                s_bins[64];
    __shared__ unsigned long long s_key[CAND_CAP];
    __shared__ int                s_cnt;
    __shared__ int                s_tstar;
    __shared__ unsigned int       s_thresh;

    const int t = threadIdx.x;

    // --- per-thread chunk sum over 64 consecutive bins ---
    int s = 0;
#pragma unroll 4
    for (int b = t * 64; b < t * 64 + 64; ++b) s += (int)g_hist[b];
    s_sum[t] = s;
    __syncthreads();

    // --- Hillis-Steele suffix scan: s_sum[t] = sum over chunks t..1023 ---
    for (int d = 1; d < 1024; d <<= 1) {
        int v = s_sum[t] + ((t + d < 1024) ? s_sum[t + d] : 0);
        __syncthreads();
        s_sum[t] = v;
        __syncthreads();
    }

    // --- find chunk containing rank 512 (counting from the top) ---
    if (s_sum[t] >= KSEL && (t == 1023 || s_sum[t + 1] < KSEL)) s_tstar = t;
    __syncthreads();
    const int tstar = s_tstar;

    if (t < 64) s_bins[t] = (int)g_hist[tstar * 64 + t];
    __syncthreads();

    if (t == 0) {
        int cum = (tstar < 1023) ? s_sum[tstar + 1] : 0;
        for (int b = 63; b >= 0; --b) {
            cum += s_bins[b];
            if (cum >= KSEL) { s_thresh = ((unsigned int)(tstar * 64 + b)) << 16; break; }
        }
        s_cnt = 0;
    }
    __syncthreads();
    const unsigned int T = s_thresh;

    // --- compact candidates: atomics fire only on the ~540 hits ---
    for (int i = t; i < N_KEYS; i += 1024) {
        unsigned int u = ford(g_sims[i]);
        if (u >= T) {
            int p = atomicAdd(&s_cnt, 1);
            if (p < CAND_CAP)
                s_key[p] = ((unsigned long long)u << 32) | (unsigned int)(~(unsigned int)i);
        }
    }
    __syncthreads();
    const int cnt = (s_cnt < CAND_CAP) ? s_cnt : CAND_CAP;
    for (int i = t; i < CAND_CAP; i += 1024)
        if (i >= cnt) s_key[i] = 0ull;                 // pad sorts last
    __syncthreads();

    // --- bitonic sort, descending (value desc; tie -> smaller index first) ---
    for (int k = 2; k <= CAND_CAP; k <<= 1) {
        for (int j = k >> 1; j > 0; j >>= 1) {
#pragma unroll
            for (int ii = 0; ii < 2; ++ii) {
                int i = t + ii * 1024;
                int ixj = i ^ j;
                if (ixj > i) {
                    unsigned long long a = s_key[i];
                    unsigned long long b = s_key[ixj];
                    bool desc = ((i & k) == 0);
                    bool sw   = desc ? (a < b) : (a > b);
                    if (sw) { s_key[i] = b; s_key[ixj] = a; }
                }
            }
            __syncthreads();
        }
    }

    if (t < KSEL)
        g_topk[t] = (int)(~(unsigned int)(s_key[t] & 0xFFFFFFFFull));
}

// ---------------------------------------------------------------------
// Kernel C: out[b,k,:] = x[b,k,:] + prompts[topk[k], :]
// One block per (b,k) row; thread t handles float4 t of the row.
// prompts' 512 selected rows (2 MB) stay L2-resident across all 128 batches.
// ---------------------------------------------------------------------
__global__ void add_kernel(const float4* __restrict__ x,
                           const float4* __restrict__ prompts,
                           float4* __restrict__ out) {
    const int bid = blockIdx.x;            // b*512 + k
    const int k   = bid & (KSEL - 1);
    const int t   = threadIdx.x;           // 0..255
    const int row = g_topk[k];

    const size_t xo = (size_t)bid * (EMB / 4) + t;
    float4 xv = x[xo];
    float4 pv = __ldg(&prompts[(size_t)row * (EMB / 4) + t]);
    xv.x += pv.x; xv.y += pv.y; xv.z += pv.z; xv.w += pv.w;
    out[xo] = xv;
}

// ---------------------------------------------------------------------
extern "C" void kernel_launch(void* const* d_in, const int* in_sizes, int n_in,
                              void* d_out, int out_size) {
    const float* x       = (const float*)d_in[0];   // [128, 512, 1024]
    const float* query   = (const float*)d_in[1];   // [1024]
    const float* keys    = (const float*)d_in[2];   // [65536, 1024]
    const float* prompts = (const float*)d_in[3];   // [65536, 1024]
    float* out           = (float*)d_out;           // [128, 512, 1024]

    zero_hist_kernel<<<64, 1024>>>();
    sim_kernel<<<N_KEYS / 8, 256>>>(keys, query);
    topk_kernel<<<1, 1024>>>();
    add_kernel<<<BATCH * KSEL, 256>>>(reinterpret_cast<const float4*>(x),
                                      reinterpret_cast<const float4*>(prompts),
                                      reinterpret_cast<float4*>(out));
}

// round 3
// speedup vs baseline: 1.1986x; 1.1986x over previous
#include <cuda_runtime.h>
#include <cstdint>

// Problem constants (fixed by the reference).
#define N_KEYS   65536
#define EMB      1024
#define KSEL     512
#define BATCH    128
#define CAND_CAP 2048    // candidate capacity (expected ~540 used; huge margin)

// -------- scratch (no allocations allowed: __device__ globals) --------
// NOTE: zero-initialized at module load; topk_kernel re-zeroes g_hist after
// consuming it, so every call (correctness run + each graph replay) starts
// from a zeroed histogram without a separate zeroing launch.
__device__ float        g_sims[N_KEYS];
__device__ unsigned int g_hist[65536];   // histogram over top-16 bits of ordered float
__device__ int          g_topk[KSEL];

// Monotone float -> uint transform: a > b  <=>  ford(a) > ford(b)
__device__ __forceinline__ unsigned int ford(float f) {
    unsigned int u = __float_as_uint(f);
    return (u & 0x80000000u) ? ~u : (u | 0x80000000u);
}

// ---------------------------------------------------------------------
// Kernel A: sims[n] = dot(keys[n], query) / ||keys[n]||  (+ histogram)
// One warp per key row. 8 warps / block, grid = 8192.  (DRAM-bound, ~43us)
// ---------------------------------------------------------------------
__global__ void sim_kernel(const float* __restrict__ keys,
                           const float* __restrict__ query) {
    const int warp = threadIdx.x >> 5;
    const int lane = threadIdx.x & 31;
    const int n    = blockIdx.x * 8 + warp;

    const float4* k4 = reinterpret_cast<const float4*>(keys) + (size_t)n * (EMB / 4);
    const float4* q4 = reinterpret_cast<const float4*>(query);

    float dot = 0.f, sq = 0.f;
#pragma unroll
    for (int l = 0; l < 8; ++l) {
        float4 kv = k4[lane + 32 * l];
        float4 qv = __ldg(&q4[lane + 32 * l]);
        dot = fmaf(kv.x, qv.x, dot);
        dot = fmaf(kv.y, qv.y, dot);
        dot = fmaf(kv.z, qv.z, dot);
        dot = fmaf(kv.w, qv.w, dot);
        sq  = fmaf(kv.x, kv.x, sq);
        sq  = fmaf(kv.y, kv.y, sq);
        sq  = fmaf(kv.z, kv.z, sq);
        sq  = fmaf(kv.w, kv.w, sq);
    }
#pragma unroll
    for (int o = 16; o > 0; o >>= 1) {
        dot += __shfl_xor_sync(0xFFFFFFFFu, dot, o);
        sq  += __shfl_xor_sync(0xFFFFFFFFu, sq,  o);
    }
    if (lane == 0) {
        float nrm = __fsqrt_rn(fmaxf(sq, 1e-16f));   // max(norm, 1e-8)
        float sim = __fdiv_rn(dot, nrm);             // q-norm scale omitted (order-invariant)
        g_sims[n] = sim;
        atomicAdd(&g_hist[ford(sim) >> 16], 1u);
    }
}

// ---------------------------------------------------------------------
// Kernel B: single block, 1024 threads.
//   1) suffix-scan of 65536-bin histogram -> rank-512 prefix threshold
//   2) compact candidates (ord >= threshold) -> ~540 entries in smem
//   3) O(n^2) rank placement: rank(i) = #{j : key_j > key_i},
//      key = (ord<<32)|~idx  => exact top_k order (desc value, asc index)
//   4) re-zero g_hist for the next call (graph replay invariant)
// ---------------------------------------------------------------------
__global__ void topk_kernel() {
    __shared__ int                s_sum[1024];     // chunk sums -> suffix sums
    __shared__ int                s_bins[64];
    __shared__ unsigned long long s_key[CAND_CAP];
    __shared__ int                s_cnt;
    __shared__ int                s_tstar;
    __shared__ unsigned int       s_thresh;

    const int t = threadIdx.x;

    // --- per-thread chunk sum over 64 consecutive bins (16x uint4) ---
    {
        const uint4* h4 = reinterpret_cast<const uint4*>(g_hist) + t * 16;
        unsigned int s = 0;
#pragma unroll
        for (int i = 0; i < 16; ++i) {
            uint4 v = h4[i];
            s += v.x + v.y + v.z + v.w;
        }
        s_sum[t] = (int)s;
    }
    __syncthreads();

    // --- Hillis-Steele suffix scan: s_sum[t] = sum over chunks t..1023 ---
    for (int d = 1; d < 1024; d <<= 1) {
        int v = s_sum[t] + ((t + d < 1024) ? s_sum[t + d] : 0);
        __syncthreads();
        s_sum[t] = v;
        __syncthreads();
    }

    // --- find chunk containing rank 512 (counting from the top) ---
    if (s_sum[t] >= KSEL && (t == 1023 || s_sum[t + 1] < KSEL)) s_tstar = t;
    __syncthreads();
    const int tstar = s_tstar;

    if (t < 64) s_bins[t] = (int)g_hist[tstar * 64 + t];
    __syncthreads();

    if (t == 0) {
        int cum = (tstar < 1023) ? s_sum[tstar + 1] : 0;
        for (int b = 63; b >= 0; --b) {
            cum += s_bins[b];
            if (cum >= KSEL) { s_thresh = ((unsigned int)(tstar * 64 + b)) << 16; break; }
        }
        s_cnt = 0;
    }
    __syncthreads();
    const unsigned int T = s_thresh;

    // --- compact candidates (vectorized read; atomics fire ~540 times) ---
    {
        const float4* s4 = reinterpret_cast<const float4*>(g_sims);
#pragma unroll
        for (int blk = 0; blk < N_KEYS / 4096; ++blk) {   // 16 iters of 1024 thr * float4
            int i4 = blk * 1024 + t;
            float4 v = s4[i4];
            unsigned int u0 = ford(v.x), u1 = ford(v.y), u2 = ford(v.z), u3 = ford(v.w);
            int base = i4 * 4;
            if (u0 >= T) { int p = atomicAdd(&s_cnt, 1); if (p < CAND_CAP)
                s_key[p] = ((unsigned long long)u0 << 32) | (unsigned int)~(unsigned int)(base + 0); }
            if (u1 >= T) { int p = atomicAdd(&s_cnt, 1); if (p < CAND_CAP)
                s_key[p] = ((unsigned long long)u1 << 32) | (unsigned int)~(unsigned int)(base + 1); }
            if (u2 >= T) { int p = atomicAdd(&s_cnt, 1); if (p < CAND_CAP)
                s_key[p] = ((unsigned long long)u2 << 32) | (unsigned int)~(unsigned int)(base + 2); }
            if (u3 >= T) { int p = atomicAdd(&s_cnt, 1); if (p < CAND_CAP)
                s_key[p] = ((unsigned long long)u3 << 32) | (unsigned int)~(unsigned int)(base + 3); }
        }
    }
    __syncthreads();
    const int cnt = (s_cnt < CAND_CAP) ? s_cnt : CAND_CAP;

    // --- O(n^2) rank placement: each thread owns candidates t, t+1024, ... ---
    for (int i = t; i < cnt; i += 1024) {
        const unsigned long long ki = s_key[i];
        int rank = 0;
        for (int j = 0; j < cnt; ++j)              // broadcast smem reads
            rank += (s_key[j] > ki);
        if (rank < KSEL)
            g_topk[rank] = (int)(~(unsigned int)(ki & 0xFFFFFFFFull));
    }

    // --- re-zero histogram for the next invocation (no extra launch) ---
    {
        uint4 z = make_uint4(0u, 0u, 0u, 0u);
        uint4* h4 = reinterpret_cast<uint4*>(g_hist) + t * 16;
#pragma unroll
        for (int i = 0; i < 16; ++i) h4[i] = z;
    }
}

// ---------------------------------------------------------------------
// Kernel C: out[b,k,:] = x[b,k,:] + prompts[topk[k], :]
// One block per (b,k) row; thread t handles float4 t of the row.
// The 512 selected prompt rows (2 MB) stay L2-resident across all batches.
// ---------------------------------------------------------------------
__global__ void add_kernel(const float4* __restrict__ x,
                           const float4* __restrict__ prompts,
                           float4* __restrict__ out) {
    const int bid = blockIdx.x;            // b*512 + k
    const int k   = bid & (KSEL - 1);
    const int t   = threadIdx.x;           // 0..255
    const int row = g_topk[k];

    const size_t xo = (size_t)bid * (EMB / 4) + t;
    float4 xv = x[xo];
    float4 pv = __ldg(&prompts[(size_t)row * (EMB / 4) + t]);
    xv.x += pv.x; xv.y += pv.y; xv.z += pv.z; xv.w += pv.w;
    out[xo] = xv;
}

// ---------------------------------------------------------------------
extern "C" void kernel_launch(void* const* d_in, const int* in_sizes, int n_in,
                              void* d_out, int out_size) {
    const float* x       = (const float*)d_in[0];   // [128, 512, 1024]
    const float* query   = (const float*)d_in[1];   // [1024]
    const float* keys    = (const float*)d_in[2];   // [65536, 1024]
    const float* prompts = (const float*)d_in[3];   // [65536, 1024]
    float* out           = (float*)d_out;           // [128, 512, 1024]

    sim_kernel<<<N_KEYS / 8, 256>>>(keys, query);
    topk_kernel<<<1, 1024>>>();
    add_kernel<<<BATCH * KSEL, 256>>>(reinterpret_cast<const float4*>(x),
                                      reinterpret_cast<const float4*>(prompts),
                                      reinterpret_cast<float4*>(out));
}